// round 7
// baseline (speedup 1.0000x reference)
#include <cuda_runtime.h>
#include <cuda_fp16.h>

#define NPTS (1 << 19)
#define NG 64
#define NVOX (64 * 64 * 64)
#define NBINS 32768   // 15-bit Morton cells (32^3)

// ---------------- static device scratch (allocation-free) ----------------
__device__ float4 g_xf[NG * 3];            // fused (rot*scale*31.5 | bias) rows
__device__ float2 g_w2[32];                // W2 as float2 pairs
__device__ uint2  g_feat8[NG * NVOX];      // 128 MB: Morton-voxel x-dup fp16 (2ch)
__device__ unsigned g_F[NPTS * 64];        // 128 MB: features [slot][128] fp16 (half2 words)
__device__ uint2  g_W0frag[8 * 8 * 32];    // mma B-fragments, layer0: [kt][nt][lane]
__device__ uint2  g_W1frag[4 * 8 * 32];    // mma B-fragments, layer1
__device__ int    g_hist[NBINS];           // Morton-cell histogram
__device__ int    g_binoff[NBINS];         // running bin offsets (rebuilt every launch)
__device__ float4 g_xs[NPTS];              // sorted points: (x,y,z, bitcast(orig idx))

static __device__ __forceinline__ unsigned long long ffma2(
    unsigned long long a, unsigned long long b, unsigned long long c) {
  unsigned long long d;
  asm("fma.rn.f32x2 %0, %1, %2, %3;" : "=l"(d) : "l"(a), "l"(b), "l"(c));
  return d;
}
static __device__ __forceinline__ unsigned long long pack2(float a, float b) {
  unsigned long long r;
  asm("mov.b64 %0, {%1, %2};" : "=l"(r) : "f"(a), "f"(b));
  return r;
}
static __device__ __forceinline__ float2 unpack2(unsigned long long v) {
  float2 r;
  asm("mov.b64 {%0, %1}, %2;" : "=f"(r.x), "=f"(r.y) : "l"(v));
  return r;
}
static __device__ __forceinline__ unsigned pack_h2(float a, float b) {
  __half2 h = __floats2half2_rn(a, b);
  return *reinterpret_cast<unsigned*>(&h);
}
static __device__ __forceinline__ void mma16816(float* d, const unsigned* a, uint2 b) {
  asm volatile(
      "mma.sync.aligned.m16n8k16.row.col.f32.f16.f16.f32 "
      "{%0,%1,%2,%3}, {%4,%5,%6,%7}, {%8,%9}, {%0,%1,%2,%3};"
      : "+f"(d[0]), "+f"(d[1]), "+f"(d[2]), "+f"(d[3])
      : "r"(a[0]), "r"(a[1]), "r"(a[2]), "r"(a[3]), "r"(b.x), "r"(b.y));
}
// spread 6 bits b5..b0 to positions 15,12,9,6,3,0
static __device__ __forceinline__ unsigned spread6(unsigned v) {
  v = (v | (v << 8)) & 0x0300F00Fu;
  v = (v | (v << 4)) & 0x030C30C3u;
  v = (v | (v << 2)) & 0x09249249u;
  return v;
}
// compact 3-bit morton: bits 0,3,6 -> 0,1,2
static __device__ __forceinline__ int compact3(int v) {
  return (v & 1) | ((v >> 2) & 2) | ((v >> 4) & 4);
}
static __device__ __forceinline__ int part1by2_5(int v) {
  v &= 0x1f;
  v = (v | (v << 8)) & 0x100F;
  v = (v | (v << 4)) & 0x10C3;
  v = (v | (v << 2)) & 0x1249;
  return v;
}
static __device__ __forceinline__ int morton_cell(float px, float py, float pz) {
  int ix = min(31, max(0, (int)((px + 1.0f) * 16.0f)));
  int iy = min(31, max(0, (int)((py + 1.0f) * 16.0f)));
  int iz = min(31, max(0, (int)((pz + 1.0f) * 16.0f)));
  return part1by2_5(ix) | (part1by2_5(iy) << 1) | (part1by2_5(iz) << 2);
}

// ---------------------------------------------------------------------------
// Kernel 0: affine fold + W2 stage + W0/W1 mma-fragment swizzle + hist zero.
// ---------------------------------------------------------------------------
__global__ void k_prep(const float* __restrict__ r, const float* __restrict__ s,
                       const float* __restrict__ t, const float* __restrict__ w2,
                       const float* __restrict__ W0, const float* __restrict__ W1) {
  int tid = threadIdx.x;
  if (tid < NG) {
    int g = tid;
    float qw = r[g * 4 + 0], qx = r[g * 4 + 1], qy = r[g * 4 + 2], qz = r[g * 4 + 3];
    float inv = 1.0f / sqrtf(qw * qw + qx * qx + qy * qy + qz * qz);
    qw *= inv; qx *= inv; qy *= inv; qz *= inv;
    float R[9];
    R[0] = 1.f - 2.f * (qy * qy + qz * qz); R[1] = 2.f * (qx * qy - qw * qz); R[2] = 2.f * (qx * qz + qw * qy);
    R[3] = 2.f * (qx * qy + qw * qz); R[4] = 1.f - 2.f * (qx * qx + qz * qz); R[5] = 2.f * (qy * qz - qw * qx);
    R[6] = 2.f * (qx * qz - qw * qy); R[7] = 2.f * (qy * qz + qw * qx); R[8] = 1.f - 2.f * (qx * qx + qy * qy);
#pragma unroll
    for (int i = 0; i < 3; i++) {
      float si = 31.5f * s[g * 3 + i];
      g_xf[g * 3 + i] = make_float4(si * R[i * 3 + 0], si * R[i * 3 + 1], si * R[i * 3 + 2],
                                    31.5f * t[g * 3 + i] + 31.5f);
    }
    reinterpret_cast<float*>(g_w2)[g] = w2[g];
  }
  for (int i = tid; i < NBINS; i += blockDim.x) g_hist[i] = 0;
  // W0 fragments: 8 ktiles x 8 ntiles x 32 lanes
  for (int i = tid; i < 8 * 8 * 32; i += blockDim.x) {
    int kt = i >> 8, nt = (i >> 5) & 7, lane = i & 31;
    int grp = lane >> 2, pr = lane & 3;
    int n = nt * 8 + grp;
    int k0 = kt * 16 + pr * 2;
    uint2 b;
    b.x = pack_h2(W0[n * 128 + k0], W0[n * 128 + k0 + 1]);
    b.y = pack_h2(W0[n * 128 + k0 + 8], W0[n * 128 + k0 + 9]);
    g_W0frag[i] = b;
  }
  // W1 fragments: 4 ktiles x 8 ntiles x 32 lanes
  for (int i = tid; i < 4 * 8 * 32; i += blockDim.x) {
    int kt = i >> 8, nt = (i >> 5) & 7, lane = i & 31;
    int grp = lane >> 2, pr = lane & 3;
    int n = nt * 8 + grp;
    int k0 = kt * 16 + pr * 2;
    uint2 b;
    b.x = pack_h2(W1[n * 64 + k0], W1[n * 64 + k0 + 1]);
    b.y = pack_h2(W1[n * 64 + k0 + 8], W1[n * 64 + k0 + 9]);
    g_W1frag[i] = b;
  }
}

// ---------------------------------------------------------------------------
// Sort pass 1: histogram of Morton cells.
// ---------------------------------------------------------------------------
__global__ void k_hist(const float* __restrict__ x) {
  int pt = blockIdx.x * 256 + threadIdx.x;
  int c = morton_cell(x[pt * 3 + 0], x[pt * 3 + 1], x[pt * 3 + 2]);
  atomicAdd(&g_hist[c], 1);
}

// ---------------------------------------------------------------------------
// Sort pass 2: exclusive prefix sum over 32K bins (single block, 1024 thr).
// ---------------------------------------------------------------------------
__global__ void k_scan() {
  __shared__ int wsum[32];
  int t = threadIdx.x;
  int base = t * (NBINS / 1024);      // 32 bins per thread
  int loc[32];
  int s = 0;
#pragma unroll
  for (int i = 0; i < 32; i++) { loc[i] = s; s += g_hist[base + i]; }
  int lane = t & 31, wid = t >> 5;
  int v = s;
#pragma unroll
  for (int d = 1; d < 32; d <<= 1) {
    int n = __shfl_up_sync(0xffffffffu, v, d);
    if (lane >= d) v += n;
  }
  if (lane == 31) wsum[wid] = v;
  __syncthreads();
  if (wid == 0) {
    int w = wsum[lane];
#pragma unroll
    for (int d = 1; d < 32; d <<= 1) {
      int n = __shfl_up_sync(0xffffffffu, w, d);
      if (lane >= d) w += n;
    }
    wsum[lane] = w;
  }
  __syncthreads();
  int exc = (v - s) + (wid > 0 ? wsum[wid - 1] : 0);
#pragma unroll
  for (int i = 0; i < 32; i++) g_binoff[base + i] = exc + loc[i];
}

// ---------------------------------------------------------------------------
// Sort pass 3: scatter points into Morton order, carrying original index.
// ---------------------------------------------------------------------------
__global__ void k_scatter(const float* __restrict__ x) {
  int pt = blockIdx.x * 256 + threadIdx.x;
  float px = x[pt * 3 + 0], py = x[pt * 3 + 1], pz = x[pt * 3 + 2];
  int c = morton_cell(px, py, pz);
  int slot = atomicAdd(&g_binoff[c], 1);
  g_xs[slot] = make_float4(px, py, pz, __int_as_float(pt));
}

// ---------------------------------------------------------------------------
// Kernel 1: cube-blocked repack. One block per (grid, 8x8x8 cube).
// An aligned 8^3 cube = one contiguous 512-entry Morton range, so the 8B
// x-dup entries are written fully coalesced. Entry (g,x,y,z):
//   .x = (c0,c1)@x   .y = (c0,c1)@min(x+1,63)
// ---------------------------------------------------------------------------
__global__ void __launch_bounds__(128)
k_repack(const float* __restrict__ feat) {
  __shared__ float sv[2][8][8][9];   // [ch][dz][dy][dx], dx has +1 halo
  int b = blockIdx.x;
  int g = b >> 9;
  int c = b & 511;                   // morton cube id
  int bx = compact3(c) * 8, by = compact3(c >> 1) * 8, bz = compact3(c >> 2) * 8;
  for (int i = threadIdx.x; i < 2 * 8 * 8 * 9; i += 128) {
    int ch = i / 576;  int r  = i - ch * 576;
    int dz = r / 72;   int r2 = r - dz * 72;
    int dy = r2 / 9;   int dx = r2 - dy * 9;
    int gx = min(bx + dx, 63);
    sv[ch][dz][dy][dx] =
        feat[(((size_t)(2 * g + ch)) << 18) + (((size_t)(bz + dz)) << 12) + ((by + dy) << 6) + gx];
  }
  __syncthreads();
  uint2* op = g_feat8 + (((size_t)g) << 18) + (c << 9);
  for (int v = threadIdx.x; v < 512; v += 128) {
    int vx = compact3(v), vy = compact3(v >> 1), vz = compact3(v >> 2);
    uint2 e;
    e.x = pack_h2(sv[0][vz][vy][vx], sv[1][vz][vy][vx]);
    e.y = pack_h2(sv[0][vz][vy][vx + 1], sv[1][vz][vy][vx + 1]);
    op[v] = e;
  }
}

// ---------------------------------------------------------------------------
// Kernel 2: gather (Morton-sorted points, Morton-laid 8B x-dup voxels).
// 4 x LDG.64 per grid-point; spread6 via shared LUT.
// ---------------------------------------------------------------------------
__global__ void __launch_bounds__(256)
k_feat() {
  __shared__ unsigned slut[64];
  if (threadIdx.x < 64) slut[threadIdx.x] = spread6(threadIdx.x);
  __syncthreads();

  int slot = blockIdx.x * 256 + threadIdx.x;
  float4 p = g_xs[slot];
  float px = p.x, py = p.y, pz = p.z;
  uint4* dst = reinterpret_cast<uint4*>(&g_F[slot * 64]);

  for (int gb = 0; gb < 4; gb++) {
    unsigned feats[16];
#pragma unroll 2
    for (int gi = 0; gi < 16; gi++) {
      int g = gb * 16 + gi;
      float4 m0 = __ldg(&g_xf[g * 3 + 0]);
      float4 m1 = __ldg(&g_xf[g * 3 + 1]);
      float4 m2 = __ldg(&g_xf[g * 3 + 2]);
      float gx = fmaf(m0.x, px, fmaf(m0.y, py, fmaf(m0.z, pz, m0.w)));
      float gy = fmaf(m1.x, px, fmaf(m1.y, py, fmaf(m1.z, pz, m1.w)));
      float gz = fmaf(m2.x, px, fmaf(m2.y, py, fmaf(m2.z, pz, m2.w)));
      float xf0 = floorf(gx), yf0 = floorf(gy), zf0 = floorf(gz);
      int x0 = (int)xf0, y0 = (int)yf0, z0 = (int)zf0;
      float fx = gx - xf0, fy = gy - yf0, fz = gz - zf0;

      int lx  = min(max(x0, 0), 63);
      int ly0 = min(max(y0, 0), 63);
      int ly1 = min(max(y0 + 1, 0), 63);
      int lz0 = min(max(z0, 0), 63);
      int lz1 = min(max(z0 + 1, 0), 63);
      unsigned mx  = slut[lx];
      unsigned my0 = slut[ly0] << 1, my1 = slut[ly1] << 1;
      unsigned mz0 = slut[lz0] << 2, mz1 = slut[lz1] << 2;
      const uint2* fb = g_feat8 + ((size_t)g << 18);
      uint2 qa = __ldg(fb + (mx | my0 | mz0));   // (y0, z0): x0, x1
      uint2 qb = __ldg(fb + (mx | my1 | mz0));   // (y1, z0)
      uint2 qc = __ldg(fb + (mx | my0 | mz1));   // (y0, z1)
      uint2 qd = __ldg(fb + (mx | my1 | mz1));   // (y1, z1)

      float wx1 = (x0 >= -1 && x0 < 63) ? fx : 0.f;
      float wx0 = (x0 >= 0 && x0 < 64) ? (1.f - fx) : 0.f;
      float wy1 = (y0 >= -1 && y0 < 63) ? fy : 0.f;
      float wy0 = (y0 >= 0 && y0 < 64) ? (1.f - fy) : 0.f;
      float wz1 = (z0 >= -1 && z0 < 63) ? fz : 0.f;
      float wz0 = (z0 >= 0 && z0 < 64) ? (1.f - fz) : 0.f;

      bool sx = x0 < 0;
      unsigned c00 = qa.x, c01 = sx ? qa.x : qa.y;
      unsigned c10 = qb.x, c11 = sx ? qb.x : qb.y;
      unsigned d00 = qc.x, d01 = sx ? qc.x : qc.y;
      unsigned d10 = qd.x, d11 = sx ? qd.x : qd.y;

      float wzy00 = wz0 * wy0, wzy01 = wz0 * wy1, wzy10 = wz1 * wy0, wzy11 = wz1 * wy1;

      unsigned long long accA = 0ull, accB = 0ull;
      {
        float2 v;
        __half2 hv;
        hv = *reinterpret_cast<__half2*>(&c00); v = __half22float2(hv);
        accA = ffma2(pack2(wzy00 * wx0, wzy00 * wx0), pack2(v.x, v.y), accA);
        hv = *reinterpret_cast<__half2*>(&c01); v = __half22float2(hv);
        accB = ffma2(pack2(wzy00 * wx1, wzy00 * wx1), pack2(v.x, v.y), accB);
        hv = *reinterpret_cast<__half2*>(&c10); v = __half22float2(hv);
        accA = ffma2(pack2(wzy01 * wx0, wzy01 * wx0), pack2(v.x, v.y), accA);
        hv = *reinterpret_cast<__half2*>(&c11); v = __half22float2(hv);
        accB = ffma2(pack2(wzy01 * wx1, wzy01 * wx1), pack2(v.x, v.y), accB);
        hv = *reinterpret_cast<__half2*>(&d00); v = __half22float2(hv);
        accA = ffma2(pack2(wzy10 * wx0, wzy10 * wx0), pack2(v.x, v.y), accA);
        hv = *reinterpret_cast<__half2*>(&d01); v = __half22float2(hv);
        accB = ffma2(pack2(wzy10 * wx1, wzy10 * wx1), pack2(v.x, v.y), accB);
        hv = *reinterpret_cast<__half2*>(&d10); v = __half22float2(hv);
        accA = ffma2(pack2(wzy11 * wx0, wzy11 * wx0), pack2(v.x, v.y), accA);
        hv = *reinterpret_cast<__half2*>(&d11); v = __half22float2(hv);
        accB = ffma2(pack2(wzy11 * wx1, wzy11 * wx1), pack2(v.x, v.y), accB);
      }
      float2 fa = unpack2(accA), fbv = unpack2(accB);
      feats[gi] = pack_h2(fa.x + fbv.x, fa.y + fbv.y);
    }
#pragma unroll
    for (int j = 0; j < 4; j++) {
      dst[gb * 4 + j] = make_uint4(feats[4 * j], feats[4 * j + 1],
                                   feats[4 * j + 2], feats[4 * j + 3]);
    }
  }
}

// ---------------------------------------------------------------------------
// Kernel 3: MLP via HMMA m16n8k16 over sorted rows; outputs scattered back
// to original point order via the index carried in g_xs.w.
// ---------------------------------------------------------------------------
__global__ void __launch_bounds__(128)
k_mlp(float* __restrict__ out) {
  __shared__ unsigned Fs[128 * 68];   // rows padded to 68 words (136 halves)
  int t = threadIdx.x;
  int pt0 = blockIdx.x * 128;
  const uint4* src = reinterpret_cast<const uint4*>(&g_F[pt0 * 64]);
#pragma unroll
  for (int j = 0; j < 16; j++) {
    int i = t + 128 * j;
    int row = i >> 4, w = i & 15;
    *reinterpret_cast<uint4*>(&Fs[row * 68 + w * 4]) = __ldg(&src[i]);
  }
  __syncthreads();

  int lane = t & 31, warp = t >> 5;
  int grp = lane >> 2, pr = lane & 3;
  int rb = warp * 32;

  float acc[2][8][4];
#pragma unroll
  for (int mt = 0; mt < 2; mt++)
#pragma unroll
    for (int nt = 0; nt < 8; nt++)
#pragma unroll
      for (int q = 0; q < 4; q++) acc[mt][nt][q] = 0.f;

  // ---- layer 0 ----
#pragma unroll
  for (int kt = 0; kt < 8; kt++) {
    unsigned a[2][4];
#pragma unroll
    for (int mt = 0; mt < 2; mt++) {
      const unsigned* r0 = &Fs[(rb + mt * 16 + grp) * 68 + kt * 8 + pr];
      const unsigned* r1 = r0 + 8 * 68;
      a[mt][0] = r0[0]; a[mt][1] = r1[0]; a[mt][2] = r0[4]; a[mt][3] = r1[4];
    }
#pragma unroll
    for (int nt = 0; nt < 8; nt++) {
      uint2 b = __ldg(&g_W0frag[(kt * 8 + nt) * 32 + lane]);
      mma16816(acc[0][nt], a[0], b);
      mma16816(acc[1][nt], a[1], b);
    }
  }

  // ---- layer 1 ----
  float acc1[2][8][4];
#pragma unroll
  for (int mt = 0; mt < 2; mt++)
#pragma unroll
    for (int nt = 0; nt < 8; nt++)
#pragma unroll
      for (int q = 0; q < 4; q++) acc1[mt][nt][q] = 0.f;

#pragma unroll
  for (int kt = 0; kt < 4; kt++) {
    unsigned a[2][4];
#pragma unroll
    for (int mt = 0; mt < 2; mt++) {
      a[mt][0] = pack_h2(fmaxf(acc[mt][2 * kt][0], 0.f), fmaxf(acc[mt][2 * kt][1], 0.f));
      a[mt][1] = pack_h2(fmaxf(acc[mt][2 * kt][2], 0.f), fmaxf(acc[mt][2 * kt][3], 0.f));
      a[mt][2] = pack_h2(fmaxf(acc[mt][2 * kt + 1][0], 0.f), fmaxf(acc[mt][2 * kt + 1][1], 0.f));
      a[mt][3] = pack_h2(fmaxf(acc[mt][2 * kt + 1][2], 0.f), fmaxf(acc[mt][2 * kt + 1][3], 0.f));
    }
#pragma unroll
    for (int nt = 0; nt < 8; nt++) {
      uint2 b = __ldg(&g_W1frag[(kt * 8 + nt) * 32 + lane]);
      mma16816(acc1[0][nt], a[0], b);
      mma16816(acc1[1][nt], a[1], b);
    }
  }

  // ---- output: scatter back to original order ----
#pragma unroll
  for (int mt = 0; mt < 2; mt++) {
    float p0 = 0.f, p1 = 0.f;
#pragma unroll
    for (int nt = 0; nt < 8; nt++) {
      float2 w = __ldg(&g_w2[nt * 4 + pr]);
      p0 = fmaf(fmaxf(acc1[mt][nt][0], 0.f), w.x, p0);
      p0 = fmaf(fmaxf(acc1[mt][nt][1], 0.f), w.y, p0);
      p1 = fmaf(fmaxf(acc1[mt][nt][2], 0.f), w.x, p1);
      p1 = fmaf(fmaxf(acc1[mt][nt][3], 0.f), w.y, p1);
    }
    p0 += __shfl_xor_sync(0xffffffffu, p0, 1);
    p0 += __shfl_xor_sync(0xffffffffu, p0, 2);
    p1 += __shfl_xor_sync(0xffffffffu, p1, 1);
    p1 += __shfl_xor_sync(0xffffffffu, p1, 2);
    if (pr == 0) {
      int row0 = pt0 + rb + mt * 16 + grp;
      int i0 = __float_as_int(g_xs[row0].w);
      int i1 = __float_as_int(g_xs[row0 + 8].w);
      out[i0] = p0;
      out[i1] = p1;
    }
  }
}

extern "C" void kernel_launch(void* const* d_in, const int* in_sizes, int n_in,
                              void* d_out, int out_size) {
  const float* x  = (const float*)d_in[0];
  const float* r  = (const float*)d_in[1];
  const float* s  = (const float*)d_in[2];
  const float* t  = (const float*)d_in[3];
  const float* fe = (const float*)d_in[4];
  const float* W0 = (const float*)d_in[5];
  const float* W1 = (const float*)d_in[6];
  const float* W2 = (const float*)d_in[7];
  float* out = (float*)d_out;
  (void)in_sizes; (void)n_in; (void)out_size;

  k_prep<<<1, 256>>>(r, s, t, W2, W0, W1);
  k_hist<<<NPTS / 256, 256>>>(x);
  k_scan<<<1, 1024>>>();
  k_scatter<<<NPTS / 256, 256>>>(x);
  k_repack<<<NG * 512, 128>>>(fe);
  k_feat<<<NPTS / 256, 256>>>();
  k_mlp<<<NPTS / 128, 128>>>(out);
}

// round 8
// speedup vs baseline: 1.1793x; 1.1793x over previous
#include <cuda_runtime.h>
#include <cuda_fp16.h>

#define NPTS (1 << 19)
#define NG 64
#define NVOX (64 * 64 * 64)
#define NBINS 32768   // 15-bit Morton cells (32^3)

// ---------------- static device scratch (allocation-free) ----------------
__device__ float4 g_xf[NG * 3];            // fused (rot*scale*31.5 | bias) rows
__device__ float2 g_w2[32];                // W2 as float2 pairs
__device__ uint4  g_feat[NG * NVOX];       // 256 MB: Morton-voxel 2x2 (y,x) corner-dup fp16
__device__ uint2  g_W0frag[8 * 8 * 32];    // mma B-fragments, layer0: [kt][nt][lane]
__device__ uint2  g_W1frag[4 * 8 * 32];    // mma B-fragments, layer1
__device__ int    g_hist[NBINS];           // Morton-cell histogram
__device__ int    g_binoff[NBINS];         // running bin offsets (rebuilt every launch)
__device__ float4 g_xs[NPTS];              // sorted points: (x,y,z, bitcast(orig idx))

static __device__ __forceinline__ unsigned long long ffma2(
    unsigned long long a, unsigned long long b, unsigned long long c) {
  unsigned long long d;
  asm("fma.rn.f32x2 %0, %1, %2, %3;" : "=l"(d) : "l"(a), "l"(b), "l"(c));
  return d;
}
static __device__ __forceinline__ unsigned long long pack2(float a, float b) {
  unsigned long long r;
  asm("mov.b64 %0, {%1, %2};" : "=l"(r) : "f"(a), "f"(b));
  return r;
}
static __device__ __forceinline__ float2 unpack2(unsigned long long v) {
  float2 r;
  asm("mov.b64 {%0, %1}, %2;" : "=f"(r.x), "=f"(r.y) : "l"(v));
  return r;
}
static __device__ __forceinline__ unsigned pack_h2(float a, float b) {
  __half2 h = __floats2half2_rn(a, b);
  return *reinterpret_cast<unsigned*>(&h);
}
static __device__ __forceinline__ void mma16816(float* d, const unsigned* a, uint2 b) {
  asm volatile(
      "mma.sync.aligned.m16n8k16.row.col.f32.f16.f16.f32 "
      "{%0,%1,%2,%3}, {%4,%5,%6,%7}, {%8,%9}, {%0,%1,%2,%3};"
      : "+f"(d[0]), "+f"(d[1]), "+f"(d[2]), "+f"(d[3])
      : "r"(a[0]), "r"(a[1]), "r"(a[2]), "r"(a[3]), "r"(b.x), "r"(b.y));
}
// spread 6 bits b5..b0 to positions 15,12,9,6,3,0
static __device__ __forceinline__ unsigned spread6(unsigned v) {
  v = (v | (v << 8)) & 0x0300F00Fu;
  v = (v | (v << 4)) & 0x030C30C3u;
  v = (v | (v << 2)) & 0x09249249u;
  return v;
}
// compact 3-bit morton: bits 0,3,6 -> 0,1,2
static __device__ __forceinline__ int compact3(int v) {
  return (v & 1) | ((v >> 2) & 2) | ((v >> 4) & 4);
}
static __device__ __forceinline__ int part1by2_5(int v) {
  v &= 0x1f;
  v = (v | (v << 8)) & 0x100F;
  v = (v | (v << 4)) & 0x10C3;
  v = (v | (v << 2)) & 0x1249;
  return v;
}
static __device__ __forceinline__ int morton_cell(float px, float py, float pz) {
  int ix = min(31, max(0, (int)((px + 1.0f) * 16.0f)));
  int iy = min(31, max(0, (int)((py + 1.0f) * 16.0f)));
  int iz = min(31, max(0, (int)((pz + 1.0f) * 16.0f)));
  return part1by2_5(ix) | (part1by2_5(iy) << 1) | (part1by2_5(iz) << 2);
}

// ---------------------------------------------------------------------------
// Kernel 0: affine fold + W2 stage + W0/W1 mma-fragment swizzle + hist zero.
// ---------------------------------------------------------------------------
__global__ void k_prep(const float* __restrict__ r, const float* __restrict__ s,
                       const float* __restrict__ t, const float* __restrict__ w2,
                       const float* __restrict__ W0, const float* __restrict__ W1) {
  int tid = threadIdx.x;
  if (tid < NG) {
    int g = tid;
    float qw = r[g * 4 + 0], qx = r[g * 4 + 1], qy = r[g * 4 + 2], qz = r[g * 4 + 3];
    float inv = 1.0f / sqrtf(qw * qw + qx * qx + qy * qy + qz * qz);
    qw *= inv; qx *= inv; qy *= inv; qz *= inv;
    float R[9];
    R[0] = 1.f - 2.f * (qy * qy + qz * qz); R[1] = 2.f * (qx * qy - qw * qz); R[2] = 2.f * (qx * qz + qw * qy);
    R[3] = 2.f * (qx * qy + qw * qz); R[4] = 1.f - 2.f * (qx * qx + qz * qz); R[5] = 2.f * (qy * qz - qw * qx);
    R[6] = 2.f * (qx * qz - qw * qy); R[7] = 2.f * (qy * qz + qw * qx); R[8] = 1.f - 2.f * (qx * qx + qy * qy);
#pragma unroll
    for (int i = 0; i < 3; i++) {
      float si = 31.5f * s[g * 3 + i];
      g_xf[g * 3 + i] = make_float4(si * R[i * 3 + 0], si * R[i * 3 + 1], si * R[i * 3 + 2],
                                    31.5f * t[g * 3 + i] + 31.5f);
    }
    reinterpret_cast<float*>(g_w2)[g] = w2[g];
  }
  for (int i = tid; i < NBINS; i += blockDim.x) g_hist[i] = 0;
  // W0 fragments: 8 ktiles x 8 ntiles x 32 lanes
  for (int i = tid; i < 8 * 8 * 32; i += blockDim.x) {
    int kt = i >> 8, nt = (i >> 5) & 7, lane = i & 31;
    int grp = lane >> 2, pr = lane & 3;
    int n = nt * 8 + grp;
    int k0 = kt * 16 + pr * 2;
    uint2 b;
    b.x = pack_h2(W0[n * 128 + k0], W0[n * 128 + k0 + 1]);
    b.y = pack_h2(W0[n * 128 + k0 + 8], W0[n * 128 + k0 + 9]);
    g_W0frag[i] = b;
  }
  // W1 fragments: 4 ktiles x 8 ntiles x 32 lanes
  for (int i = tid; i < 4 * 8 * 32; i += blockDim.x) {
    int kt = i >> 8, nt = (i >> 5) & 7, lane = i & 31;
    int grp = lane >> 2, pr = lane & 3;
    int n = nt * 8 + grp;
    int k0 = kt * 16 + pr * 2;
    uint2 b;
    b.x = pack_h2(W1[n * 64 + k0], W1[n * 64 + k0 + 1]);
    b.y = pack_h2(W1[n * 64 + k0 + 8], W1[n * 64 + k0 + 9]);
    g_W1frag[i] = b;
  }
}

// ---------------------------------------------------------------------------
// Sort pass 1: histogram of Morton cells.
// ---------------------------------------------------------------------------
__global__ void k_hist(const float* __restrict__ x) {
  int pt = blockIdx.x * 256 + threadIdx.x;
  int c = morton_cell(x[pt * 3 + 0], x[pt * 3 + 1], x[pt * 3 + 2]);
  atomicAdd(&g_hist[c], 1);
}

// ---------------------------------------------------------------------------
// Sort pass 2: exclusive prefix sum over 32K bins (single block, 1024 thr).
// ---------------------------------------------------------------------------
__global__ void k_scan() {
  __shared__ int wsum[32];
  int t = threadIdx.x;
  int base = t * (NBINS / 1024);      // 32 bins per thread
  int loc[32];
  int s = 0;
#pragma unroll
  for (int i = 0; i < 32; i++) { loc[i] = s; s += g_hist[base + i]; }
  int lane = t & 31, wid = t >> 5;
  int v = s;
#pragma unroll
  for (int d = 1; d < 32; d <<= 1) {
    int n = __shfl_up_sync(0xffffffffu, v, d);
    if (lane >= d) v += n;
  }
  if (lane == 31) wsum[wid] = v;
  __syncthreads();
  if (wid == 0) {
    int w = wsum[lane];
#pragma unroll
    for (int d = 1; d < 32; d <<= 1) {
      int n = __shfl_up_sync(0xffffffffu, w, d);
      if (lane >= d) w += n;
    }
    wsum[lane] = w;
  }
  __syncthreads();
  int exc = (v - s) + (wid > 0 ? wsum[wid - 1] : 0);
#pragma unroll
  for (int i = 0; i < 32; i++) g_binoff[base + i] = exc + loc[i];
}

// ---------------------------------------------------------------------------
// Sort pass 3: scatter points into Morton order, carrying original index.
// ---------------------------------------------------------------------------
__global__ void k_scatter(const float* __restrict__ x) {
  int pt = blockIdx.x * 256 + threadIdx.x;
  float px = x[pt * 3 + 0], py = x[pt * 3 + 1], pz = x[pt * 3 + 2];
  int c = morton_cell(px, py, pz);
  int slot = atomicAdd(&g_binoff[c], 1);
  g_xs[slot] = make_float4(px, py, pz, __int_as_float(pt));
}

// ---------------------------------------------------------------------------
// Kernel 1: cube-blocked repack -> 16B (y,x) corner-dup entries at Morton
// addresses. One block per (grid, 8x8x8 cube); x,y halo staged in shared;
// 512 fully-coalesced STG.128 per block.
// Entry (g,z,y,x): .x=(c0,c1)(y,x) .y=(y,x1) .z=(y1,x) .w=(y1,x1),
// x1=min(x+1,63), y1=min(y+1,63).
// ---------------------------------------------------------------------------
__global__ void __launch_bounds__(128)
k_repack(const float* __restrict__ feat) {
  __shared__ float sv[2][8][9][9];   // [ch][dz][dy(+halo)][dx(+halo)]
  int b = blockIdx.x;
  int g = b >> 9;
  int c = b & 511;                   // cube morton id
  int bx = compact3(c) * 8, by = compact3(c >> 1) * 8, bz = compact3(c >> 2) * 8;
  for (int i = threadIdx.x; i < 2 * 8 * 9 * 9; i += 128) {
    int ch = i / 648;  int r  = i - ch * 648;
    int dz = r / 81;   int r2 = r - dz * 81;
    int dy = r2 / 9;   int dx = r2 - dy * 9;
    int gx = min(bx + dx, 63);
    int gy = min(by + dy, 63);
    sv[ch][dz][dy][dx] =
        feat[(((size_t)(2 * g + ch)) << 18) + (((size_t)(bz + dz)) << 12) + (gy << 6) + gx];
  }
  __syncthreads();
  uint4* op = g_feat + (((size_t)g) << 18) + (c << 9);
  for (int v = threadIdx.x; v < 512; v += 128) {
    int vx = compact3(v), vy = compact3(v >> 1), vz = compact3(v >> 2);
    uint4 e;
    e.x = pack_h2(sv[0][vz][vy][vx],     sv[1][vz][vy][vx]);
    e.y = pack_h2(sv[0][vz][vy][vx + 1], sv[1][vz][vy][vx + 1]);
    e.z = pack_h2(sv[0][vz][vy + 1][vx],     sv[1][vz][vy + 1][vx]);
    e.w = pack_h2(sv[0][vz][vy + 1][vx + 1], sv[1][vz][vy + 1][vx + 1]);
    op[v] = e;
  }
}

// ---------------------------------------------------------------------------
// Kernel 2 (FUSED): gather + MLP. 128 points/CTA, 4 warps.
// Phase 1: each thread gathers its point's 64 half2 features (2 x LDG.128
// per grid from the Morton table) and stores them straight into the shared
// MMA staging tile (STS.128, stride-68 rows = conflict-free).
// Phase 2: HMMA m16n8k16 MLP; outputs scattered to original order.
// No global feature round-trip.
// ---------------------------------------------------------------------------
__global__ void __launch_bounds__(128)
k_fused(float* __restrict__ out) {
  __shared__ alignas(16) unsigned Fs[128 * 68];   // rows padded to 68 words
  __shared__ unsigned slut[64];
  int t = threadIdx.x;
  if (t < 64) slut[t] = spread6(t);
  __syncthreads();

  int pt0 = blockIdx.x * 128;
  int slot = pt0 + t;
  float4 p = g_xs[slot];
  float px = p.x, py = p.y, pz = p.z;

  // ---- phase 1: gather ----
  for (int gb = 0; gb < 4; gb++) {
    unsigned feats[16];
#pragma unroll 4
    for (int gi = 0; gi < 16; gi++) {
      int g = gb * 16 + gi;
      float4 m0 = __ldg(&g_xf[g * 3 + 0]);
      float4 m1 = __ldg(&g_xf[g * 3 + 1]);
      float4 m2 = __ldg(&g_xf[g * 3 + 2]);
      float gx = fmaf(m0.x, px, fmaf(m0.y, py, fmaf(m0.z, pz, m0.w)));
      float gy = fmaf(m1.x, px, fmaf(m1.y, py, fmaf(m1.z, pz, m1.w)));
      float gz = fmaf(m2.x, px, fmaf(m2.y, py, fmaf(m2.z, pz, m2.w)));
      float xf0 = floorf(gx), yf0 = floorf(gy), zf0 = floorf(gz);
      int x0 = (int)xf0, y0 = (int)yf0, z0 = (int)zf0;
      float fx = gx - xf0, fy = gy - yf0, fz = gz - zf0;

      int lx  = min(max(x0, 0), 63);
      int ly  = min(max(y0, 0), 63);
      int lz0 = min(max(z0, 0), 63);
      int lz1 = min(max(z0 + 1, 0), 63);
      unsigned mxy = slut[lx] | (slut[ly] << 1);
      const uint4* fb = g_feat + ((size_t)g << 18);
      uint4 q0 = __ldg(fb + (mxy | (slut[lz0] << 2)));
      uint4 q1 = __ldg(fb + (mxy | (slut[lz1] << 2)));

      float wx1 = (x0 >= -1 && x0 < 63) ? fx : 0.f;
      float wx0 = (x0 >= 0 && x0 < 64) ? (1.f - fx) : 0.f;
      float wy1 = (y0 >= -1 && y0 < 63) ? fy : 0.f;
      float wy0 = (y0 >= 0 && y0 < 64) ? (1.f - fy) : 0.f;
      float wz1 = (z0 >= -1 && z0 < 63) ? fz : 0.f;
      float wz0 = (z0 >= 0 && z0 < 64) ? (1.f - fz) : 0.f;

      bool sx = x0 < 0, sy = y0 < 0;
      unsigned c00 = q0.x;
      unsigned c01 = sx ? q0.x : q0.y;
      unsigned c10 = sy ? q0.x : q0.z;
      unsigned c11 = sy ? c01 : (sx ? q0.z : q0.w);
      unsigned d00 = q1.x;
      unsigned d01 = sx ? q1.x : q1.y;
      unsigned d10 = sy ? q1.x : q1.z;
      unsigned d11 = sy ? d01 : (sx ? q1.z : q1.w);

      float wzy00 = wz0 * wy0, wzy01 = wz0 * wy1, wzy10 = wz1 * wy0, wzy11 = wz1 * wy1;

      unsigned long long accA = 0ull, accB = 0ull;
      {
        float2 v;
        __half2 hv;
        hv = *reinterpret_cast<__half2*>(&c00); v = __half22float2(hv);
        accA = ffma2(pack2(wzy00 * wx0, wzy00 * wx0), pack2(v.x, v.y), accA);
        hv = *reinterpret_cast<__half2*>(&c01); v = __half22float2(hv);
        accB = ffma2(pack2(wzy00 * wx1, wzy00 * wx1), pack2(v.x, v.y), accB);
        hv = *reinterpret_cast<__half2*>(&c10); v = __half22float2(hv);
        accA = ffma2(pack2(wzy01 * wx0, wzy01 * wx0), pack2(v.x, v.y), accA);
        hv = *reinterpret_cast<__half2*>(&c11); v = __half22float2(hv);
        accB = ffma2(pack2(wzy01 * wx1, wzy01 * wx1), pack2(v.x, v.y), accB);
        hv = *reinterpret_cast<__half2*>(&d00); v = __half22float2(hv);
        accA = ffma2(pack2(wzy10 * wx0, wzy10 * wx0), pack2(v.x, v.y), accA);
        hv = *reinterpret_cast<__half2*>(&d01); v = __half22float2(hv);
        accB = ffma2(pack2(wzy10 * wx1, wzy10 * wx1), pack2(v.x, v.y), accB);
        hv = *reinterpret_cast<__half2*>(&d10); v = __half22float2(hv);
        accA = ffma2(pack2(wzy11 * wx0, wzy11 * wx0), pack2(v.x, v.y), accA);
        hv = *reinterpret_cast<__half2*>(&d11); v = __half22float2(hv);
        accB = ffma2(pack2(wzy11 * wx1, wzy11 * wx1), pack2(v.x, v.y), accB);
      }
      float2 fa = unpack2(accA), fbv = unpack2(accB);
      feats[gi] = pack_h2(fa.x + fbv.x, fa.y + fbv.y);  // feats 2g, 2g+1
    }
#pragma unroll
    for (int j = 0; j < 4; j++) {
      *reinterpret_cast<uint4*>(&Fs[t * 68 + gb * 16 + 4 * j]) =
          make_uint4(feats[4 * j], feats[4 * j + 1], feats[4 * j + 2], feats[4 * j + 3]);
    }
  }
  __syncthreads();

  // ---- phase 2: MLP ----
  int lane = t & 31, warp = t >> 5;
  int grp = lane >> 2, pr = lane & 3;
  int rb = warp * 32;

  float acc[2][8][4];
#pragma unroll
  for (int mt = 0; mt < 2; mt++)
#pragma unroll
    for (int nt = 0; nt < 8; nt++)
#pragma unroll
      for (int q = 0; q < 4; q++) acc[mt][nt][q] = 0.f;

#pragma unroll
  for (int kt = 0; kt < 8; kt++) {
    unsigned a[2][4];
#pragma unroll
    for (int mt = 0; mt < 2; mt++) {
      const unsigned* r0 = &Fs[(rb + mt * 16 + grp) * 68 + kt * 8 + pr];
      const unsigned* r1 = r0 + 8 * 68;
      a[mt][0] = r0[0]; a[mt][1] = r1[0]; a[mt][2] = r0[4]; a[mt][3] = r1[4];
    }
#pragma unroll
    for (int nt = 0; nt < 8; nt++) {
      uint2 b = __ldg(&g_W0frag[(kt * 8 + nt) * 32 + lane]);
      mma16816(acc[0][nt], a[0], b);
      mma16816(acc[1][nt], a[1], b);
    }
  }

  float acc1[2][8][4];
#pragma unroll
  for (int mt = 0; mt < 2; mt++)
#pragma unroll
    for (int nt = 0; nt < 8; nt++)
#pragma unroll
      for (int q = 0; q < 4; q++) acc1[mt][nt][q] = 0.f;

#pragma unroll
  for (int kt = 0; kt < 4; kt++) {
    unsigned a[2][4];
#pragma unroll
    for (int mt = 0; mt < 2; mt++) {
      a[mt][0] = pack_h2(fmaxf(acc[mt][2 * kt][0], 0.f), fmaxf(acc[mt][2 * kt][1], 0.f));
      a[mt][1] = pack_h2(fmaxf(acc[mt][2 * kt][2], 0.f), fmaxf(acc[mt][2 * kt][3], 0.f));
      a[mt][2] = pack_h2(fmaxf(acc[mt][2 * kt + 1][0], 0.f), fmaxf(acc[mt][2 * kt + 1][1], 0.f));
      a[mt][3] = pack_h2(fmaxf(acc[mt][2 * kt + 1][2], 0.f), fmaxf(acc[mt][2 * kt + 1][3], 0.f));
    }
#pragma unroll
    for (int nt = 0; nt < 8; nt++) {
      uint2 b = __ldg(&g_W1frag[(kt * 8 + nt) * 32 + lane]);
      mma16816(acc1[0][nt], a[0], b);
      mma16816(acc1[1][nt], a[1], b);
    }
  }

#pragma unroll
  for (int mt = 0; mt < 2; mt++) {
    float p0 = 0.f, p1 = 0.f;
#pragma unroll
    for (int nt = 0; nt < 8; nt++) {
      float2 w = __ldg(&g_w2[nt * 4 + pr]);
      p0 = fmaf(fmaxf(acc1[mt][nt][0], 0.f), w.x, p0);
      p0 = fmaf(fmaxf(acc1[mt][nt][1], 0.f), w.y, p0);
      p1 = fmaf(fmaxf(acc1[mt][nt][2], 0.f), w.x, p1);
      p1 = fmaf(fmaxf(acc1[mt][nt][3], 0.f), w.y, p1);
    }
    p0 += __shfl_xor_sync(0xffffffffu, p0, 1);
    p0 += __shfl_xor_sync(0xffffffffu, p0, 2);
    p1 += __shfl_xor_sync(0xffffffffu, p1, 1);
    p1 += __shfl_xor_sync(0xffffffffu, p1, 2);
    if (pr == 0) {
      int row0 = pt0 + rb + mt * 16 + grp;
      int i0 = __float_as_int(g_xs[row0].w);
      int i1 = __float_as_int(g_xs[row0 + 8].w);
      out[i0] = p0;
      out[i1] = p1;
    }
  }
}

extern "C" void kernel_launch(void* const* d_in, const int* in_sizes, int n_in,
                              void* d_out, int out_size) {
  const float* x  = (const float*)d_in[0];
  const float* r  = (const float*)d_in[1];
  const float* s  = (const float*)d_in[2];
  const float* t  = (const float*)d_in[3];
  const float* fe = (const float*)d_in[4];
  const float* W0 = (const float*)d_in[5];
  const float* W1 = (const float*)d_in[6];
  const float* W2 = (const float*)d_in[7];
  float* out = (float*)d_out;
  (void)in_sizes; (void)n_in; (void)out_size;

  k_prep<<<1, 256>>>(r, s, t, W2, W0, W1);
  k_hist<<<NPTS / 256, 256>>>(x);
  k_scan<<<1, 1024>>>();
  k_scatter<<<NPTS / 256, 256>>>(x);
  k_repack<<<NG * 512, 128>>>(fe);
  k_fused<<<NPTS / 128, 128>>>(out);
}

// round 12
// speedup vs baseline: 1.2269x; 1.0404x over previous
#include <cuda_runtime.h>
#include <cuda_fp16.h>

#define NPTS (1 << 19)
#define NG 64
#define NVOX (64 * 64 * 64)
#define NBINS 32768   // 15-bit Morton cells (32^3)

// ---------------- static device scratch (allocation-free) ----------------
__device__ float4 g_xf[NG * 3];            // fused (rot*scale*31.5 | bias) rows
__device__ float2 g_w2[32];                // W2 as float2 pairs
__device__ uint4  g_feat[NG * NVOX];       // 256 MB: Morton-voxel 2x2 (y,x) corner-dup fp16
__device__ uint2  g_W0frag[8 * 8 * 32];    // mma B-fragments, layer0: [kt][nt][lane]
__device__ uint2  g_W1frag[4 * 8 * 32];    // mma B-fragments, layer1
__device__ int    g_hist[NBINS];           // Morton-cell histogram
__device__ int    g_binoff[NBINS];         // running bin offsets (rebuilt every launch)
__device__ float4 g_xs[NPTS];              // sorted points: (x,y,z, bitcast(orig idx))

static __device__ __forceinline__ unsigned long long ffma2(
    unsigned long long a, unsigned long long b, unsigned long long c) {
  unsigned long long d;
  asm("fma.rn.f32x2 %0, %1, %2, %3;" : "=l"(d) : "l"(a), "l"(b), "l"(c));
  return d;
}
static __device__ __forceinline__ unsigned long long pack2(float a, float b) {
  unsigned long long r;
  asm("mov.b64 %0, {%1, %2};" : "=l"(r) : "f"(a), "f"(b));
  return r;
}
static __device__ __forceinline__ float2 unpack2(unsigned long long v) {
  float2 r;
  asm("mov.b64 {%0, %1}, %2;" : "=f"(r.x), "=f"(r.y) : "l"(v));
  return r;
}
static __device__ __forceinline__ unsigned pack_h2(float a, float b) {
  __half2 h = __floats2half2_rn(a, b);
  return *reinterpret_cast<unsigned*>(&h);
}
static __device__ __forceinline__ void mma16816(float* d, const unsigned* a, uint2 b) {
  asm volatile(
      "mma.sync.aligned.m16n8k16.row.col.f32.f16.f16.f32 "
      "{%0,%1,%2,%3}, {%4,%5,%6,%7}, {%8,%9}, {%0,%1,%2,%3};"
      : "+f"(d[0]), "+f"(d[1]), "+f"(d[2]), "+f"(d[3])
      : "r"(a[0]), "r"(a[1]), "r"(a[2]), "r"(a[3]), "r"(b.x), "r"(b.y));
}
// spread 6 bits b5..b0 to positions 15,12,9,6,3,0
static __device__ __forceinline__ unsigned spread6(unsigned v) {
  v = (v | (v << 8)) & 0x0300F00Fu;
  v = (v | (v << 4)) & 0x030C30C3u;
  v = (v | (v << 2)) & 0x09249249u;
  return v;
}
// compact 3-bit morton: bits 0,3,6 -> 0,1,2
static __device__ __forceinline__ int compact3(int v) {
  return (v & 1) | ((v >> 2) & 2) | ((v >> 4) & 4);
}
static __device__ __forceinline__ int part1by2_5(int v) {
  v &= 0x1f;
  v = (v | (v << 8)) & 0x100F;
  v = (v | (v << 4)) & 0x10C3;
  v = (v | (v << 2)) & 0x1249;
  return v;
}
static __device__ __forceinline__ int morton_cell(float px, float py, float pz) {
  int ix = min(31, max(0, (int)((px + 1.0f) * 16.0f)));
  int iy = min(31, max(0, (int)((py + 1.0f) * 16.0f)));
  int iz = min(31, max(0, (int)((pz + 1.0f) * 16.0f)));
  return part1by2_5(ix) | (part1by2_5(iy) << 1) | (part1by2_5(iz) << 2);
}

// ---------------------------------------------------------------------------
// Kernel 0: affine fold + W2 stage + W0/W1 mma-fragment swizzle + hist zero.
// ---------------------------------------------------------------------------
__global__ void k_prep(const float* __restrict__ r, const float* __restrict__ s,
                       const float* __restrict__ t, const float* __restrict__ w2,
                       const float* __restrict__ W0, const float* __restrict__ W1) {
  int tid = threadIdx.x;
  if (tid < NG) {
    int g = tid;
    float qw = r[g * 4 + 0], qx = r[g * 4 + 1], qy = r[g * 4 + 2], qz = r[g * 4 + 3];
    float inv = 1.0f / sqrtf(qw * qw + qx * qx + qy * qy + qz * qz);
    qw *= inv; qx *= inv; qy *= inv; qz *= inv;
    float R[9];
    R[0] = 1.f - 2.f * (qy * qy + qz * qz); R[1] = 2.f * (qx * qy - qw * qz); R[2] = 2.f * (qx * qz + qw * qy);
    R[3] = 2.f * (qx * qy + qw * qz); R[4] = 1.f - 2.f * (qx * qx + qz * qz); R[5] = 2.f * (qy * qz - qw * qx);
    R[6] = 2.f * (qx * qz - qw * qy); R[7] = 2.f * (qy * qz + qw * qx); R[8] = 1.f - 2.f * (qx * qx + qy * qy);
#pragma unroll
    for (int i = 0; i < 3; i++) {
      float si = 31.5f * s[g * 3 + i];
      g_xf[g * 3 + i] = make_float4(si * R[i * 3 + 0], si * R[i * 3 + 1], si * R[i * 3 + 2],
                                    31.5f * t[g * 3 + i] + 31.5f);
    }
    reinterpret_cast<float*>(g_w2)[g] = w2[g];
  }
  for (int i = tid; i < NBINS; i += blockDim.x) g_hist[i] = 0;
  // W0 fragments: 8 ktiles x 8 ntiles x 32 lanes
  for (int i = tid; i < 8 * 8 * 32; i += blockDim.x) {
    int kt = i >> 8, nt = (i >> 5) & 7, lane = i & 31;
    int grp = lane >> 2, pr = lane & 3;
    int n = nt * 8 + grp;
    int k0 = kt * 16 + pr * 2;
    uint2 b;
    b.x = pack_h2(W0[n * 128 + k0], W0[n * 128 + k0 + 1]);
    b.y = pack_h2(W0[n * 128 + k0 + 8], W0[n * 128 + k0 + 9]);
    g_W0frag[i] = b;
  }
  // W1 fragments: 4 ktiles x 8 ntiles x 32 lanes
  for (int i = tid; i < 4 * 8 * 32; i += blockDim.x) {
    int kt = i >> 8, nt = (i >> 5) & 7, lane = i & 31;
    int grp = lane >> 2, pr = lane & 3;
    int n = nt * 8 + grp;
    int k0 = kt * 16 + pr * 2;
    uint2 b;
    b.x = pack_h2(W1[n * 64 + k0], W1[n * 64 + k0 + 1]);
    b.y = pack_h2(W1[n * 64 + k0 + 8], W1[n * 64 + k0 + 9]);
    g_W1frag[i] = b;
  }
}

// ---------------------------------------------------------------------------
// Sort pass 1: histogram of Morton cells.
// ---------------------------------------------------------------------------
__global__ void k_hist(const float* __restrict__ x) {
  int pt = blockIdx.x * 256 + threadIdx.x;
  int c = morton_cell(x[pt * 3 + 0], x[pt * 3 + 1], x[pt * 3 + 2]);
  atomicAdd(&g_hist[c], 1);
}

// ---------------------------------------------------------------------------
// Sort pass 2: exclusive prefix sum over 32K bins (single block, 1024 thr).
// ---------------------------------------------------------------------------
__global__ void k_scan() {
  __shared__ int wsum[32];
  int t = threadIdx.x;
  int base = t * (NBINS / 1024);      // 32 bins per thread
  int loc[32];
  int s = 0;
#pragma unroll
  for (int i = 0; i < 32; i++) { loc[i] = s; s += g_hist[base + i]; }
  int lane = t & 31, wid = t >> 5;
  int v = s;
#pragma unroll
  for (int d = 1; d < 32; d <<= 1) {
    int n = __shfl_up_sync(0xffffffffu, v, d);
    if (lane >= d) v += n;
  }
  if (lane == 31) wsum[wid] = v;
  __syncthreads();
  if (wid == 0) {
    int w = wsum[lane];
#pragma unroll
    for (int d = 1; d < 32; d <<= 1) {
      int n = __shfl_up_sync(0xffffffffu, w, d);
      if (lane >= d) w += n;
    }
    wsum[lane] = w;
  }
  __syncthreads();
  int exc = (v - s) + (wid > 0 ? wsum[wid - 1] : 0);
#pragma unroll
  for (int i = 0; i < 32; i++) g_binoff[base + i] = exc + loc[i];
}

// ---------------------------------------------------------------------------
// Sort pass 3: scatter points into Morton order, carrying original index.
// ---------------------------------------------------------------------------
__global__ void k_scatter(const float* __restrict__ x) {
  int pt = blockIdx.x * 256 + threadIdx.x;
  float px = x[pt * 3 + 0], py = x[pt * 3 + 1], pz = x[pt * 3 + 2];
  int c = morton_cell(px, py, pz);
  int slot = atomicAdd(&g_binoff[c], 1);
  g_xs[slot] = make_float4(px, py, pz, __int_as_float(pt));
}

// ---------------------------------------------------------------------------
// Kernel 1: cube-blocked repack -> 16B (y,x) corner-dup entries at Morton
// addresses. One block per (grid, 8x8x8 cube); x,y halo staged in shared;
// 512 fully-coalesced STG.128 per block.
// ---------------------------------------------------------------------------
__global__ void __launch_bounds__(128)
k_repack(const float* __restrict__ feat) {
  __shared__ float sv[2][8][9][9];   // [ch][dz][dy(+halo)][dx(+halo)]
  int b = blockIdx.x;
  int g = b >> 9;
  int c = b & 511;                   // cube morton id
  int bx = compact3(c) * 8, by = compact3(c >> 1) * 8, bz = compact3(c >> 2) * 8;
  for (int i = threadIdx.x; i < 2 * 8 * 9 * 9; i += 128) {
    int ch = i / 648;  int r  = i - ch * 648;
    int dz = r / 81;   int r2 = r - dz * 81;
    int dy = r2 / 9;   int dx = r2 - dy * 9;
    int gx = min(bx + dx, 63);
    int gy = min(by + dy, 63);
    sv[ch][dz][dy][dx] =
        feat[(((size_t)(2 * g + ch)) << 18) + (((size_t)(bz + dz)) << 12) + (gy << 6) + gx];
  }
  __syncthreads();
  uint4* op = g_feat + (((size_t)g) << 18) + (c << 9);
  for (int v = threadIdx.x; v < 512; v += 128) {
    int vx = compact3(v), vy = compact3(v >> 1), vz = compact3(v >> 2);
    uint4 e;
    e.x = pack_h2(sv[0][vz][vy][vx],     sv[1][vz][vy][vx]);
    e.y = pack_h2(sv[0][vz][vy][vx + 1], sv[1][vz][vy][vx + 1]);
    e.z = pack_h2(sv[0][vz][vy + 1][vx],     sv[1][vz][vy + 1][vx]);
    e.w = pack_h2(sv[0][vz][vy + 1][vx + 1], sv[1][vz][vy + 1][vx + 1]);
    op[v] = e;
  }
}

// ---------------------------------------------------------------------------
// Kernel 2 (FUSED): gather + MLP. 128 points/CTA, 4 warps.
// Phase 1: gather into shared MMA tile. Phase 2: HMMA MLP with the two
// m-tiles processed SEQUENTIALLY to halve accumulator registers -> higher
// occupancy for gather latency hiding.
// ---------------------------------------------------------------------------
__global__ void __launch_bounds__(128, 4)
k_fused(float* __restrict__ out) {
  __shared__ alignas(16) unsigned Fs[128 * 68];   // rows padded to 68 words
  __shared__ unsigned slut[64];
  __shared__ alignas(16) float4 sxf[NG * 3];
  int t = threadIdx.x;
  if (t < 64) slut[t] = spread6(t);
  for (int i = t; i < NG * 3; i += 128) sxf[i] = g_xf[i];
  __syncthreads();

  int pt0 = blockIdx.x * 128;
  int slot = pt0 + t;
  float4 p = g_xs[slot];
  float px = p.x, py = p.y, pz = p.z;

  // ---- phase 1: gather ----
  for (int gb = 0; gb < 4; gb++) {
    unsigned feats[16];
#pragma unroll 4
    for (int gi = 0; gi < 16; gi++) {
      int g = gb * 16 + gi;
      float4 m0 = sxf[g * 3 + 0];
      float4 m1 = sxf[g * 3 + 1];
      float4 m2 = sxf[g * 3 + 2];
      float gx = fmaf(m0.x, px, fmaf(m0.y, py, fmaf(m0.z, pz, m0.w)));
      float gy = fmaf(m1.x, px, fmaf(m1.y, py, fmaf(m1.z, pz, m1.w)));
      float gz = fmaf(m2.x, px, fmaf(m2.y, py, fmaf(m2.z, pz, m2.w)));
      float xf0 = floorf(gx), yf0 = floorf(gy), zf0 = floorf(gz);
      int x0 = (int)xf0, y0 = (int)yf0, z0 = (int)zf0;
      float fx = gx - xf0, fy = gy - yf0, fz = gz - zf0;

      int lx  = min(max(x0, 0), 63);
      int ly  = min(max(y0, 0), 63);
      int lz0 = min(max(z0, 0), 63);
      int lz1 = min(max(z0 + 1, 0), 63);
      unsigned mxy = slut[lx] | (slut[ly] << 1);
      const uint4* fb = g_feat + ((size_t)g << 18);
      uint4 q0 = __ldg(fb + (mxy | (slut[lz0] << 2)));
      uint4 q1 = __ldg(fb + (mxy | (slut[lz1] << 2)));

      float wx1 = (x0 >= -1 && x0 < 63) ? fx : 0.f;
      float wx0 = (x0 >= 0 && x0 < 64) ? (1.f - fx) : 0.f;
      float wy1 = (y0 >= -1 && y0 < 63) ? fy : 0.f;
      float wy0 = (y0 >= 0 && y0 < 64) ? (1.f - fy) : 0.f;
      float wz1 = (z0 >= -1 && z0 < 63) ? fz : 0.f;
      float wz0 = (z0 >= 0 && z0 < 64) ? (1.f - fz) : 0.f;

      bool sx = x0 < 0, sy = y0 < 0;
      unsigned c00 = q0.x;
      unsigned c01 = sx ? q0.x : q0.y;
      unsigned c10 = sy ? q0.x : q0.z;
      unsigned c11 = sy ? c01 : (sx ? q0.z : q0.w);
      unsigned d00 = q1.x;
      unsigned d01 = sx ? q1.x : q1.y;
      unsigned d10 = sy ? q1.x : q1.z;
      unsigned d11 = sy ? d01 : (sx ? q1.z : q1.w);

      float wzy00 = wz0 * wy0, wzy01 = wz0 * wy1, wzy10 = wz1 * wy0, wzy11 = wz1 * wy1;

      unsigned long long accA = 0ull, accB = 0ull;
      {
        float2 v;
        __half2 hv;
        hv = *reinterpret_cast<__half2*>(&c00); v = __half22float2(hv);
        accA = ffma2(pack2(wzy00 * wx0, wzy00 * wx0), pack2(v.x, v.y), accA);
        hv = *reinterpret_cast<__half2*>(&c01); v = __half22float2(hv);
        accB = ffma2(pack2(wzy00 * wx1, wzy00 * wx1), pack2(v.x, v.y), accB);
        hv = *reinterpret_cast<__half2*>(&c10); v = __half22float2(hv);
        accA = ffma2(pack2(wzy01 * wx0, wzy01 * wx0), pack2(v.x, v.y), accA);
        hv = *reinterpret_cast<__half2*>(&c11); v = __half22float2(hv);
        accB = ffma2(pack2(wzy01 * wx1, wzy01 * wx1), pack2(v.x, v.y), accB);
        hv = *reinterpret_cast<__half2*>(&d00); v = __half22float2(hv);
        accA = ffma2(pack2(wzy10 * wx0, wzy10 * wx0), pack2(v.x, v.y), accA);
        hv = *reinterpret_cast<__half2*>(&d01); v = __half22float2(hv);
        accB = ffma2(pack2(wzy10 * wx1, wzy10 * wx1), pack2(v.x, v.y), accB);
        hv = *reinterpret_cast<__half2*>(&d10); v = __half22float2(hv);
        accA = ffma2(pack2(wzy11 * wx0, wzy11 * wx0), pack2(v.x, v.y), accA);
        hv = *reinterpret_cast<__half2*>(&d11); v = __half22float2(hv);
        accB = ffma2(pack2(wzy11 * wx1, wzy11 * wx1), pack2(v.x, v.y), accB);
      }
      float2 fa = unpack2(accA), fbv = unpack2(accB);
      feats[gi] = pack_h2(fa.x + fbv.x, fa.y + fbv.y);  // feats 2g, 2g+1
    }
#pragma unroll
    for (int j = 0; j < 4; j++) {
      *reinterpret_cast<uint4*>(&Fs[t * 68 + gb * 16 + 4 * j]) =
          make_uint4(feats[4 * j], feats[4 * j + 1], feats[4 * j + 2], feats[4 * j + 3]);
    }
  }
  __syncthreads();

  // ---- phase 2: MLP, m-tiles sequential (halved accumulator registers) ----
  int lane = t & 31, warp = t >> 5;
  int grp = lane >> 2, pr = lane & 3;
  int rb = warp * 32;

#pragma unroll
  for (int mt = 0; mt < 2; mt++) {
    float acc[8][4];
#pragma unroll
    for (int nt = 0; nt < 8; nt++)
#pragma unroll
      for (int q = 0; q < 4; q++) acc[nt][q] = 0.f;

    // layer 0
#pragma unroll
    for (int kt = 0; kt < 8; kt++) {
      unsigned a[4];
      const unsigned* r0 = &Fs[(rb + mt * 16 + grp) * 68 + kt * 8 + pr];
      const unsigned* r1 = r0 + 8 * 68;
      a[0] = r0[0]; a[1] = r1[0]; a[2] = r0[4]; a[3] = r1[4];
#pragma unroll
      for (int nt = 0; nt < 8; nt++) {
        uint2 b = __ldg(&g_W0frag[(kt * 8 + nt) * 32 + lane]);
        mma16816(acc[nt], a, b);
      }
    }

    // layer 1
    float acc1[8][4];
#pragma unroll
    for (int nt = 0; nt < 8; nt++)
#pragma unroll
      for (int q = 0; q < 4; q++) acc1[nt][q] = 0.f;

#pragma unroll
    for (int kt = 0; kt < 4; kt++) {
      unsigned a[4];
      a[0] = pack_h2(fmaxf(acc[2 * kt][0], 0.f), fmaxf(acc[2 * kt][1], 0.f));
      a[1] = pack_h2(fmaxf(acc[2 * kt][2], 0.f), fmaxf(acc[2 * kt][3], 0.f));
      a[2] = pack_h2(fmaxf(acc[2 * kt + 1][0], 0.f), fmaxf(acc[2 * kt + 1][1], 0.f));
      a[3] = pack_h2(fmaxf(acc[2 * kt + 1][2], 0.f), fmaxf(acc[2 * kt + 1][3], 0.f));
#pragma unroll
      for (int nt = 0; nt < 8; nt++) {
        uint2 b = __ldg(&g_W1frag[(kt * 8 + nt) * 32 + lane]);
        mma16816(acc1[nt], a, b);
      }
    }

    // output
    float p0 = 0.f, p1 = 0.f;
#pragma unroll
    for (int nt = 0; nt < 8; nt++) {
      float2 w = __ldg(&g_w2[nt * 4 + pr]);
      p0 = fmaf(fmaxf(acc1[nt][0], 0.f), w.x, p0);
      p0 = fmaf(fmaxf(acc1[nt][1], 0.f), w.y, p0);
      p1 = fmaf(fmaxf(acc1[nt][2], 0.f), w.x, p1);
      p1 = fmaf(fmaxf(acc1[nt][3], 0.f), w.y, p1);
    }
    p0 += __shfl_xor_sync(0xffffffffu, p0, 1);
    p0 += __shfl_xor_sync(0xffffffffu, p0, 2);
    p1 += __shfl_xor_sync(0xffffffffu, p1, 1);
    p1 += __shfl_xor_sync(0xffffffffu, p1, 2);
    if (pr == 0) {
      int row0 = pt0 + rb + mt * 16 + grp;
      int i0 = __float_as_int(g_xs[row0].w);
      int i1 = __float_as_int(g_xs[row0 + 8].w);
      out[i0] = p0;
      out[i1] = p1;
    }
  }
}

extern "C" void kernel_launch(void* const* d_in, const int* in_sizes, int n_in,
                              void* d_out, int out_size) {
  const float* x  = (const float*)d_in[0];
  const float* r  = (const float*)d_in[1];
  const float* s  = (const float*)d_in[2];
  const float* t  = (const float*)d_in[3];
  const float* fe = (const float*)d_in[4];
  const float* W0 = (const float*)d_in[5];
  const float* W1 = (const float*)d_in[6];
  const float* W2 = (const float*)d_in[7];
  float* out = (float*)d_out;
  (void)in_sizes; (void)n_in; (void)out_size;

  k_prep<<<1, 256>>>(r, s, t, W2, W0, W1);
  k_hist<<<NPTS / 256, 256>>>(x);
  k_scan<<<1, 1024>>>();
  k_scatter<<<NPTS / 256, 256>>>(x);
  k_repack<<<NG * 512, 128>>>(fe);
  k_fused<<<NPTS / 128, 128>>>(out);
}